// round 1
// baseline (speedup 1.0000x reference)
#include <cuda_runtime.h>
#include <math.h>

#define VOX (48*48*48)

// Intermediate h = silu(conv1(features)): [voxel][64]
__device__ float g_h[VOX * 64];

// ---------------------------------------------------------------------------
// Kernel 1: h = silu(conv3x3x3(features, w1, b1)), replicate padding.
// grid (48,48): blockIdx.x = h, blockIdx.y = d. 256 threads:
//   o  = tid & 63   (output channel)
//   wq = tid >> 6   (w quarter, 12 voxels each)
// smem: sW [8ci][27tap][65pad] weights chunk, sF [8ci][9(kd,kh)][50 wpad] features
// ---------------------------------------------------------------------------
extern "C" __global__ void __launch_bounds__(256, 3) k_conv1(
    const float* __restrict__ feat, const float* __restrict__ w1,
    const float* __restrict__ b1)
{
    extern __shared__ float sm[];
    float* sW = sm;            // 8*27*65 = 14040 floats
    float* sF = sm + 14040;    // 8*9*50  =  3600 floats

    const int h = blockIdx.x, d = blockIdx.y;
    const int tid = threadIdx.x;
    const int o = tid & 63, wq = tid >> 6;
    const int w0 = wq * 12;

    int zd[3], zh[3];
#pragma unroll
    for (int t = 0; t < 3; t++) {
        zd[t] = min(max(d + t - 1, 0), 47);
        zh[t] = min(max(h + t - 1, 0), 47);
    }

    float acc[12];
    const float bias = b1[o];
#pragma unroll
    for (int j = 0; j < 12; j++) acc[j] = bias;

#pragma unroll 1
    for (int ci0 = 0; ci0 < 32; ci0 += 8) {
        // stage weights chunk: w1 global layout [O=64][I=32][27]
        for (int g = tid; g < 13824; g += 256) {
            int oo  = g / 216;
            int r   = g % 216;
            int ci  = r / 27, tap = r % 27;
            sW[(ci * 27 + tap) * 65 + oo] = w1[(oo * 32 + ci0 + ci) * 27 + tap];
        }
        // stage feature slab: [ci][kd*3+kh][wpad 0..49], wpad-1 clamped
        for (int t = tid; t < 3600; t += 256) {
            int ci = t / 450;
            int r  = (t % 450) / 50;
            int wp = t % 50;
            int kd = r / 3, kh = r % 3;
            int zw = min(max(wp - 1, 0), 47);
            sF[t] = feat[(ci0 + ci) * VOX + (zd[kd] * 48 + zh[kh]) * 48 + zw];
        }
        __syncthreads();

#pragma unroll 1
        for (int ci = 0; ci < 8; ci++) {
#pragma unroll
            for (int r = 0; r < 9; r++) {
                float f[14];
                const float* fp = &sF[(ci * 9 + r) * 50 + w0];
#pragma unroll
                for (int t = 0; t < 14; t++) f[t] = fp[t];
#pragma unroll
                for (int kw = 0; kw < 3; kw++) {
                    float wt = sW[(ci * 27 + r * 3 + kw) * 65 + o];
#pragma unroll
                    for (int j = 0; j < 12; j++)
                        acc[j] = fmaf(wt, f[j + kw], acc[j]);
                }
            }
        }
        __syncthreads();
    }

    // SiLU + store: h[voxel][o], warp writes 32 consecutive o -> coalesced
    long base = ((long)(d * 48 + h) * 48 + w0) * 64 + o;
#pragma unroll
    for (int j = 0; j < 12; j++) {
        float a = acc[j];
        float s = a / (1.0f + __expf(-a));
        g_h[base + (long)j * 64] = s;
    }
}

// ---------------------------------------------------------------------------
// Kernel 2: per (d,h) row of 48 voxels:
//   m = w2 @ h + b2  (216 ch)  -> softmax over 8 groups of 27 -> apply to x
// smem: sH [48][65], sW2T [64][216], sM [48][217]
// ---------------------------------------------------------------------------
extern "C" __global__ void __launch_bounds__(256, 2) k_mask_apply(
    const float* __restrict__ x, const float* __restrict__ w2,
    const float* __restrict__ b2, float* __restrict__ out)
{
    extern __shared__ float sm[];
    float* sH  = sm;                  // 48*65  = 3120
    float* sW2 = sm + 3120;           // 64*216 = 13824  ([k][mc])
    float* sM  = sm + 3120 + 13824;   // 48*217 = 10416

    const int h = blockIdx.x, d = blockIdx.y;
    const int tid = threadIdx.x;

    // load h row (48 voxels x 64 ch)
    {
        long rowbase = (long)((d * 48 + h) * 48) * 64;
        for (int t = tid; t < 48 * 64; t += 256) {
            int v = t >> 6, k = t & 63;
            sH[v * 65 + k] = g_h[rowbase + t];
        }
    }
    // load w2 transposed: global [mc][64] -> sW2[k*216 + mc]
    for (int t = tid; t < 13824; t += 256) {
        int mc = t >> 6, k = t & 63;
        sW2[k * 216 + mc] = w2[t];
    }
    __syncthreads();

    // 1x1 conv: 48 voxels x 216 ch, register tiles of 4v x 4mc
    for (int tt = tid; tt < 648; tt += 256) {
        int vt = tt % 12, mct = tt / 12;
        int v0 = vt * 4, mc0 = mct * 4;
        float accm[4][4];
#pragma unroll
        for (int i = 0; i < 4; i++)
#pragma unroll
            for (int j = 0; j < 4; j++) accm[i][j] = b2[mc0 + j];
#pragma unroll 4
        for (int k = 0; k < 64; k++) {
            float hv[4], wv[4];
#pragma unroll
            for (int i = 0; i < 4; i++) hv[i] = sH[(v0 + i) * 65 + k];
#pragma unroll
            for (int j = 0; j < 4; j++) wv[j] = sW2[k * 216 + mc0 + j];
#pragma unroll
            for (int i = 0; i < 4; i++)
#pragma unroll
                for (int j = 0; j < 4; j++)
                    accm[i][j] = fmaf(hv[i], wv[j], accm[i][j]);
        }
#pragma unroll
        for (int i = 0; i < 4; i++)
#pragma unroll
            for (int j = 0; j < 4; j++)
                sM[(v0 + i) * 217 + mc0 + j] = accm[i][j];
    }
    __syncthreads();

    // softmax over each group of 27 (8 groups per voxel), in place
    for (int g = tid; g < 48 * 8; g += 256) {
        int v = g >> 3, grp = g & 7;
        float* p = &sM[v * 217 + grp * 27];
        float mx = p[0];
#pragma unroll
        for (int n = 1; n < 27; n++) mx = fmaxf(mx, p[n]);
        float e[27];
        float s = 0.0f;
#pragma unroll
        for (int n = 0; n < 27; n++) { e[n] = __expf(p[n] - mx); s += e[n]; }
        float inv = 1.0f / s;
#pragma unroll
        for (int n = 0; n < 27; n++) p[n] = e[n] * inv;
    }
    __syncthreads();

    // apply: each slot = (voxel v, channel pair c / c+16); 768 slots
    int zd[3], zh[3];
#pragma unroll
    for (int t = 0; t < 3; t++) {
        zd[t] = min(max(d + t - 1, 0), 47);
        zh[t] = min(max(h + t - 1, 0), 47);
    }

    for (int p = tid; p < 768; p += 256) {
        int v  = p % 48;     // consecutive tid -> consecutive v (coalesced I/O)
        int cp = p / 48;     // 0..15 -> channels cp and cp+16
        int zw[3];
        zw[0] = max(v - 1, 0); zw[1] = v; zw[2] = min(v + 1, 47);

        float t0[27], t1[27];
#pragma unroll
        for (int dz = 0; dz < 3; dz++)
#pragma unroll
            for (int dy = 0; dy < 3; dy++)
#pragma unroll
                for (int dx = 0; dx < 3; dx++) {
                    long idx = ((long)zd[dz] * 48 + zh[dy]) * 48 + zw[dx];
                    int n = dz * 9 + dy * 3 + dx;
                    t0[n] = x[(long)cp * VOX + idx];
                    t1[n] = x[(long)(cp + 16) * VOX + idx];
                }

        float a0[8], a1[8];
#pragma unroll
        for (int g = 0; g < 8; g++) { a0[g] = 0.0f; a1[g] = 0.0f; }
        const float* wm = &sM[v * 217];
#pragma unroll
        for (int g = 0; g < 8; g++) {
#pragma unroll
            for (int n = 0; n < 27; n++) {
                float m = wm[g * 27 + n];
                a0[g] = fmaf(m, t0[n], a0[g]);
                a1[g] = fmaf(m, t1[n], a1[g]);
            }
        }

        // out[c][2d+i][2h+j][2w+k]; k packed into float2 (2w even -> aligned)
#pragma unroll
        for (int i = 0; i < 2; i++)
#pragma unroll
            for (int j = 0; j < 2; j++) {
                int g0 = i * 4 + j * 2;
                long ob0 = (((long)cp * 96 + 2 * d + i) * 96 + 2 * h + j) * 96 + 2 * v;
                long ob1 = (((long)(cp + 16) * 96 + 2 * d + i) * 96 + 2 * h + j) * 96 + 2 * v;
                *(float2*)(out + ob0) = make_float2(a0[g0], a0[g0 + 1]);
                *(float2*)(out + ob1) = make_float2(a1[g0], a1[g0 + 1]);
            }
    }
}

// ---------------------------------------------------------------------------
extern "C" void kernel_launch(void* const* d_in, const int* in_sizes, int n_in,
                              void* d_out, int out_size)
{
    const float* x    = (const float*)d_in[0];
    const float* feat = (const float*)d_in[1];
    const float* w1   = (const float*)d_in[2];
    const float* b1   = (const float*)d_in[3];
    const float* w2   = (const float*)d_in[4];
    const float* b2   = (const float*)d_in[5];
    float* out = (float*)d_out;

    const int smem1 = (14040 + 3600) * 4;            // 70560 B
    const int smem2 = (3120 + 13824 + 10416) * 4;    // 109440 B
    cudaFuncSetAttribute(k_conv1, cudaFuncAttributeMaxDynamicSharedMemorySize, smem1);
    cudaFuncSetAttribute(k_mask_apply, cudaFuncAttributeMaxDynamicSharedMemorySize, smem2);

    dim3 grid(48, 48);
    k_conv1<<<grid, 256, smem1>>>(feat, w1, b1);
    k_mask_apply<<<grid, 256, smem2>>>(x, w2, b2, out);
}